// round 14
// baseline (speedup 1.0000x reference)
#include <cuda_runtime.h>
#include <cuda_fp16.h>
#include <cstdint>
#include <cstddef>

#define S_LEN 2048
#define E_DIM 4096
#define H_NUM 16
#define D_DIM 256
#define RD_DIM 64
#define EW (E_DIM / 2)   // u32 words per E row
#define SW (S_LEN / 2)   // u32 words per S row

// ---------------- scratch ----------------
__device__ __align__(16) float g_V[(size_t)S_LEN * E_DIM];
__device__ __align__(16) float g_RS[(size_t)H_NUM * S_LEN];

__device__ __align__(16) uint32_t g_HH[(size_t)S_LEN * EW];
__device__ __align__(16) uint32_t g_QH[(size_t)S_LEN * EW];
__device__ __align__(16) uint32_t g_KH[(size_t)S_LEN * EW];
__device__ __align__(16) uint32_t g_AH[(size_t)S_LEN * EW];
__device__ __align__(16) uint32_t g_WH[(size_t)E_DIM * EW];
__device__ __align__(16) uint32_t g_VTH[(size_t)H_NUM * D_DIM * SW];
__device__ __align__(16) uint32_t g_PH[(size_t)H_NUM * S_LEN * SW];

// ---------------- helpers ----------------
__device__ __forceinline__ uint32_t pack_split(float x, float y, uint32_t& lo) {
    __half2 h = __floats2half2_rn(x, y);
    float rx = x - __half2float(h.x);
    float ry = y - __half2float(h.y);
    __half2 l = __floats2half2_rn(rx, ry);
    lo = *reinterpret_cast<uint32_t*>(&l);
    return *reinterpret_cast<uint32_t*>(&h);
}

__device__ __forceinline__ uint32_t pack_f16(float x, float y) {
    __half2 h = __floats2half2_rn(x, y);
    return *reinterpret_cast<uint32_t*>(&h);
}

__device__ __forceinline__ uint32_t smem_u32(const void* p) {
    uint32_t a;
    asm("{ .reg .u64 t; cvta.to.shared.u64 t, %1; cvt.u32.u64 %0, t; }" : "=r"(a) : "l"(p));
    return a;
}

__device__ __forceinline__ void mma16(float c[4], const uint32_t a[4],
                                      uint32_t b0, uint32_t b1) {
    asm volatile(
        "mma.sync.aligned.m16n8k16.row.col.f32.f16.f16.f32 "
        "{%0,%1,%2,%3},{%4,%5,%6,%7},{%8,%9},{%0,%1,%2,%3};\n"
        : "+f"(c[0]), "+f"(c[1]), "+f"(c[2]), "+f"(c[3])
        : "r"(a[0]), "r"(a[1]), "r"(a[2]), "r"(a[3]), "r"(b0), "r"(b1));
}

__device__ __forceinline__ void ldsm4(uint32_t r[4], uint32_t addr) {
    asm volatile("ldmatrix.sync.aligned.m8n8.x4.shared.b16 {%0,%1,%2,%3}, [%4];"
                 : "=r"(r[0]), "=r"(r[1]), "=r"(r[2]), "=r"(r[3]) : "r"(addr));
}

__device__ __forceinline__ void cpa16(uint32_t dst, const uint32_t* src) {
    asm volatile("cp.async.cg.shared.global [%0], [%1], 16;" :: "r"(dst), "l"(src));
}
__device__ __forceinline__ void cpa_commit() {
    asm volatile("cp.async.commit_group;" ::: "memory");
}
template<int N>
__device__ __forceinline__ void cpa_wait() {
    asm volatile("cp.async.wait_group %0;" :: "n"(N) : "memory");
}

// ---------------- GEMM: 128 x 256 C tiles, mma.sync + ldmatrix, fp16 multi-pass ----------------
// A: M x K K-major hi/lo planes of fp16x2 words. B: N x K same.
// NPASS==1: acc = A_hi*B_hi
// NPASS==2: acc = A_hi*B_hi + A_lo*B_hi
// NPASS==3: acc = A_hi*B_hi + A_hi*B_lo + A_lo*B_hi
// EPI: 0 = f32 C; 1 = fp16 split C (CL optional, rscale optional per-row scale);
//      2 = RoPE + fp16 split C; 3 = causal mask + exp(alpha*x - 2) -> fp16 CH.
#define BM 128
#define BN 256
#define ASTR 20
#define A_PL (128 * ASTR)             // 2560
#define B_PL (256 * ASTR)             // 5120
#define STG_W (2 * A_PL + 2 * B_PL)   // 15360 words = 61440 B
#define NSTAGE 3
#define SMEM_GEMM (NSTAGE * STG_W * 4)   // 184320 B

template<bool SKIP_UPPER, bool KLIMIT, int NPASS, int EPI>
__global__ void __launch_bounds__(256, 1)
gemm_ls(const uint32_t* __restrict__ aH, const uint32_t* __restrict__ aL,
        int lda, size_t sA,
        const uint32_t* __restrict__ bH, const uint32_t* __restrict__ bL,
        int ldb, size_t sB,
        float* __restrict__ C, uint32_t* __restrict__ CH, uint32_t* __restrict__ CL,
        int ldc, size_t sC,
        int K, float alpha, const int* __restrict__ pos,
        const float* __restrict__ rscale)
{
    if (SKIP_UPPER && 2 * blockIdx.x > blockIdx.y) return;
    aH += blockIdx.z * sA;  if (NPASS >= 2) aL += blockIdx.z * sA;
    bH += blockIdx.z * sB;  if (NPASS == 3) bL += blockIdx.z * sB;
    if (EPI == 1 || EPI == 2 || EPI == 3) { CH += blockIdx.z * sC; if (CL) CL += blockIdx.z * sC; }
    else { C += blockIdx.z * sC; }
    if (EPI == 1 && rscale) rscale += (size_t)blockIdx.z * S_LEN;

    const int bm = blockIdx.y * BM;
    const int bn = blockIdx.x * BN;
    const int Keff  = KLIMIT ? min(K, (int)(blockIdx.y + 1) * BM) : K;
    const int niter = Keff >> 5;          // 32 k-elems (16 words) per iter

    extern __shared__ uint32_t sm[];
    const uint32_t sb = smem_u32(sm);

    const int tid  = threadIdx.x;
    const int lane = tid & 31;
    const int warp = tid >> 5;
    const int wm   = (warp >> 2) * 64;    // 2 warps in m
    const int wn   = (warp & 3) * 64;     // 4 warps in n
    const int lr   = lane >> 2;
    const int lc   = lane & 3;

    const uint32_t* aP[2] = { aH + (size_t)bm * lda,
                              (NPASS >= 2) ? aL + (size_t)bm * lda : aH + (size_t)bm * lda };
    const uint32_t* bP[2] = { bH + (size_t)bn * ldb,
                              (NPASS == 3) ? bL + (size_t)bn * ldb : bH + (size_t)bn * ldb };

    const int loffA = ((lane & 15) + wm) * ASTR + ((lane >> 4) << 2);
    const int loffB = ((lane & 7) + ((lane >> 4) << 3) + wn) * ASTR + (((lane >> 3) & 1) << 2);

    auto issue = [&](int it) {
        const int k0w = it << 4;
        const uint32_t stg = sb + (it % NSTAGE) * (STG_W * 4);
        const int nAq = (NPASS >= 2) ? 4 : 2;
#pragma unroll
        for (int i = 0; i < 4; i++) {
            if (i >= nAq) break;
            int lin = i * 256 + tid;
            int pl = lin >> 9, rem = lin & 511;
            int row = rem >> 2, q = rem & 3;
            cpa16(stg + (pl * A_PL + row * ASTR + q * 4) * 4,
                  aP[pl] + (size_t)row * lda + k0w + q * 4);
        }
        const int nBq = (NPASS == 3) ? 8 : 4;
#pragma unroll
        for (int i = 0; i < 8; i++) {
            if (i >= nBq) break;
            int lin = i * 256 + tid;
            int pl = lin >> 10, rem = lin & 1023;
            int row = rem >> 2, q = rem & 3;
            cpa16(stg + (2 * A_PL + pl * B_PL + row * ASTR + q * 4) * 4,
                  bP[pl] + (size_t)row * ldb + k0w + q * 4);
        }
        cpa_commit();
    };

    float acc[4][8][4];
#pragma unroll
    for (int i = 0; i < 4; i++)
#pragma unroll
        for (int j = 0; j < 8; j++)
#pragma unroll
            for (int r = 0; r < 4; r++) acc[i][j][r] = 0.f;

    issue(0);
    if (niter > 1) issue(1);

    for (int it = 0; it < niter; ++it) {
        if (it + 2 < niter) { issue(it + 2); cpa_wait<2>(); }
        else if (it + 1 < niter) cpa_wait<1>();
        else cpa_wait<0>();
        __syncthreads();

        const uint32_t stg = sb + (it % NSTAGE) * (STG_W * 4);
        const uint32_t AHs = stg;
        const uint32_t ALs = AHs + A_PL * 4;
        const uint32_t BHs = ALs + A_PL * 4;
        const uint32_t BLs = BHs + B_PL * 4;

#pragma unroll
        for (int kk = 0; kk < 16; kk += 8) {
            uint32_t ah[4][4], al[4][4], bh[4][4], bl[4][4];
#pragma unroll
            for (int mt = 0; mt < 4; mt++) {
                ldsm4(ah[mt], AHs + (loffA + mt * 16 * ASTR + kk) * 4);
                if (NPASS >= 2)
                    ldsm4(al[mt], ALs + (loffA + mt * 16 * ASTR + kk) * 4);
            }
#pragma unroll
            for (int p = 0; p < 4; p++) {
                ldsm4(bh[p], BHs + (loffB + p * 16 * ASTR + kk) * 4);
                if (NPASS == 3)
                    ldsm4(bl[p], BLs + (loffB + p * 16 * ASTR + kk) * 4);
            }
#pragma unroll
            for (int mt = 0; mt < 4; mt++)
#pragma unroll
                for (int p = 0; p < 4; p++) {
#pragma unroll
                    for (int half = 0; half < 2; half++) {
                        int nt = 2 * p + half;
                        uint32_t b0h = bh[p][2 * half], b1h = bh[p][2 * half + 1];
                        mma16(acc[mt][nt], ah[mt], b0h, b1h);
                        if (NPASS >= 2)
                            mma16(acc[mt][nt], al[mt], b0h, b1h);
                        if (NPASS == 3) {
                            uint32_t b0l = bl[p][2 * half], b1l = bl[p][2 * half + 1];
                            mma16(acc[mt][nt], ah[mt], b0l, b1l);
                        }
                    }
                }
        }
        __syncthreads();
    }

    // ---- epilogue ----
#pragma unroll
    for (int mt = 0; mt < 4; mt++) {
        const int r0 = bm + wm + mt * 16 + lr;
        float p0 = 0.f, p1 = 0.f;
        if (EPI == 2) { p0 = (float)pos[r0]; p1 = (float)pos[r0 + 8]; }
        float rs0 = 1.f, rs1 = 1.f;
        if (EPI == 1 && rscale) { rs0 = rscale[r0]; rs1 = rscale[r0 + 8]; }
#pragma unroll
        for (int nt = 0; nt < 8; nt++) {
            int c0 = bn + wn + nt * 8 + lc * 2;   // even
            float a0 = acc[mt][nt][0], a1 = acc[mt][nt][1];
            float a2 = acc[mt][nt][2], a3 = acc[mt][nt][3];
            if (EPI == 3) {
                // causal mask + shift-invariant exp -> unnormalized fp16 E
                a0 = (c0     <= r0    ) ? __expf(a0 * alpha - 2.f) : 0.f;
                a1 = (c0 + 1 <= r0    ) ? __expf(a1 * alpha - 2.f) : 0.f;
                a2 = (c0     <= r0 + 8) ? __expf(a2 * alpha - 2.f) : 0.f;
                a3 = (c0 + 1 <= r0 + 8) ? __expf(a3 * alpha - 2.f) : 0.f;
                size_t o0 = (size_t)r0 * ldc + (c0 >> 1);
                size_t o1 = (size_t)(r0 + 8) * ldc + (c0 >> 1);
                CH[o0] = pack_f16(a0, a1);
                CH[o1] = pack_f16(a2, a3);
                continue;
            }
            if (EPI == 2) {
                int hoff = c0 & (D_DIM - 1);
                if (hoff < RD_DIM) {
                    float inv = exp2f(-0.41524101186092033f * (float)(hoff >> 1));
                    float sn, cs;
                    __sincosf(p0 * inv, &sn, &cs);
                    float t0 = a0 * cs - a1 * sn;
                    a1 = a1 * cs + a0 * sn;  a0 = t0;
                    __sincosf(p1 * inv, &sn, &cs);
                    float t2 = a2 * cs - a3 * sn;
                    a3 = a3 * cs + a2 * sn;  a2 = t2;
                }
            }
            if (EPI == 1 || EPI == 2) {
                float s0 = alpha * rs0, s1 = alpha * rs1;
                uint32_t lo0, lo1;
                uint32_t hi0 = pack_split(a0 * s0, a1 * s0, lo0);
                uint32_t hi1 = pack_split(a2 * s1, a3 * s1, lo1);
                size_t o0 = (size_t)r0 * ldc + (c0 >> 1);
                size_t o1 = (size_t)(r0 + 8) * ldc + (c0 >> 1);
                CH[o0] = hi0;
                CH[o1] = hi1;
                if (CL) { CL[o0] = lo0; CL[o1] = lo1; }
            } else if (EPI == 0) {
                float2 v0 = make_float2(a0 * alpha, a1 * alpha);
                float2 v1 = make_float2(a2 * alpha, a3 * alpha);
                *reinterpret_cast<float2*>(C + (size_t)r0 * ldc + c0)       = v0;
                *reinterpret_cast<float2*>(C + (size_t)(r0 + 8) * ldc + c0) = v1;
            }
        }
    }
}

// ---------------- split f32 row-major -> fp16 hi k-pair words ----------------
__global__ void split2(const float* __restrict__ in, uint32_t* __restrict__ oh)
{
    size_t i = (size_t)blockIdx.x * 256 + threadIdx.x;
    float4 v = reinterpret_cast<const float4*>(in)[i];
    reinterpret_cast<uint2*>(oh)[i] = make_uint2(pack_f16(v.x, v.y), pack_f16(v.z, v.w));
}

// ---------------- transpose+split: f32 [K][N] -> hi (and optionally lo) [N][K/2 words] ----------------
__global__ void tsplit(const float* __restrict__ in, int ldin, size_t sIn,
                       uint32_t* __restrict__ oh, uint32_t* __restrict__ ol,
                       int ldo, size_t sOut)
{
    in += blockIdx.z * sIn;
    oh += blockIdx.z * sOut;
    if (ol) ol += blockIdx.z * sOut;
    const int k0 = blockIdx.x * 32, n0 = blockIdx.y * 32;
    __shared__ float ts[32][33];
    const int tx = threadIdx.x, ty = threadIdx.y;   // 16 x 16
#pragma unroll
    for (int j = 0; j < 2; j++) {
        float2 v = *reinterpret_cast<const float2*>(
            in + (size_t)(k0 + ty + j * 16) * ldin + n0 + tx * 2);
        ts[ty + j * 16][tx * 2]     = v.x;
        ts[ty + j * 16][tx * 2 + 1] = v.y;
    }
    __syncthreads();
#pragma unroll
    for (int j = 0; j < 2; j++) {
        int n = ty + j * 16;
        uint32_t lo;
        uint32_t hi = pack_split(ts[tx * 2][n], ts[tx * 2 + 1][n], lo);
        size_t o = (size_t)(n0 + n) * ldo + (k0 >> 1) + tx;
        oh[o] = hi;
        if (ol) ol[o] = lo;
    }
}

// ---------------- rowsum: 1/sum of unnormalized fp16 E per causal row ----------------
__global__ void rowsum(const uint32_t* __restrict__ PH, float* __restrict__ RS)
{
    const int m = blockIdx.x, h = blockIdx.y, tid = threadIdx.x;   // 128 threads
    const uint32_t* row = PH + ((size_t)h * S_LEN + m) * SW;
    const int nw = (m + 2) >> 1;   // words covering cols 0..m (odd tail is zeroed)
    float s = 0.f;
    for (int w = tid; w < nw; w += 128) {
        __half2 hv = *reinterpret_cast<const __half2*>(row + w);
        float2 f = __half22float2(hv);
        s += f.x + f.y;
    }
#pragma unroll
    for (int o = 16; o; o >>= 1) s += __shfl_xor_sync(0xffffffffu, s, o);
    __shared__ float sh[4];
    if ((tid & 31) == 0) sh[tid >> 5] = s;
    __syncthreads();
    if (tid == 0) {
        float t = sh[0] + sh[1] + sh[2] + sh[3];
        RS[(size_t)h * S_LEN + m] = 1.f / t;
    }
}

// ---------------- launch ----------------
extern "C" void kernel_launch(void* const* d_in, const int* in_sizes, int n_in,
                              void* d_out, int out_size)
{
    const float* hidden = (const float*)d_in[0];
    const float* wq     = (const float*)d_in[1];
    const float* wk     = (const float*)d_in[2];
    const float* wv     = (const float*)d_in[3];
    const float* wo     = (const float*)d_in[4];
    const int*   pos    = (const int*)d_in[5];
    float* out = (float*)d_out;

    float *V, *RS;
    uint32_t *HH, *QH, *KH, *AH, *WH, *VTH, *PH;
    cudaGetSymbolAddress((void**)&V, g_V);
    cudaGetSymbolAddress((void**)&RS, g_RS);
    cudaGetSymbolAddress((void**)&HH, g_HH);
    cudaGetSymbolAddress((void**)&QH, g_QH);
    cudaGetSymbolAddress((void**)&KH, g_KH);
    cudaGetSymbolAddress((void**)&AH, g_AH);
    cudaGetSymbolAddress((void**)&WH, g_WH);
    cudaGetSymbolAddress((void**)&VTH, g_VTH);
    cudaGetSymbolAddress((void**)&PH, g_PH);

    cudaFuncSetAttribute(gemm_ls<false, false, 1, 2>, cudaFuncAttributeMaxDynamicSharedMemorySize, SMEM_GEMM);
    cudaFuncSetAttribute(gemm_ls<false, false, 1, 0>, cudaFuncAttributeMaxDynamicSharedMemorySize, SMEM_GEMM);
    cudaFuncSetAttribute(gemm_ls<true,  false, 1, 3>, cudaFuncAttributeMaxDynamicSharedMemorySize, SMEM_GEMM);
    cudaFuncSetAttribute(gemm_ls<false, true,  1, 1>, cudaFuncAttributeMaxDynamicSharedMemorySize, SMEM_GEMM);

    const dim3 b256(256);
    const dim3 tblk(16, 16);
    const dim3 gw(E_DIM / 32, E_DIM / 32, 1);
    const dim3 gproj(E_DIM / BN, S_LEN / BM, 1);
    const int nsplit = (S_LEN * E_DIM / 4) / 256;

    // hidden -> fp16
    split2<<<nsplit, b256>>>(hidden, HH);

    // Q projection: 1-pass, fused RoPE epilogue -> QH
    tsplit<<<gw, tblk>>>(wq, E_DIM, 0, WH, nullptr, EW, 0);
    gemm_ls<false, false, 1, 2><<<gproj, b256, SMEM_GEMM>>>(
        HH, HH, EW, 0, WH, nullptr, EW, 0, nullptr, QH, nullptr, EW, 0, E_DIM, 1.f, pos, nullptr);

    // K projection: 1-pass, fused RoPE epilogue -> KH
    tsplit<<<gw, tblk>>>(wk, E_DIM, 0, WH, nullptr, EW, 0);
    gemm_ls<false, false, 1, 2><<<gproj, b256, SMEM_GEMM>>>(
        HH, HH, EW, 0, WH, nullptr, EW, 0, nullptr, KH, nullptr, EW, 0, E_DIM, 1.f, pos, nullptr);

    // V projection: 1-pass, f32 out
    tsplit<<<gw, tblk>>>(wv, E_DIM, 0, WH, nullptr, EW, 0);
    gemm_ls<false, false, 1, 0><<<gproj, b256, SMEM_GEMM>>>(
        HH, HH, EW, 0, WH, nullptr, EW, 0, V, nullptr, nullptr, E_DIM, 0, E_DIM, 1.f, nullptr, nullptr);

    // V transpose+split per head (hi plane only)
    tsplit<<<dim3(S_LEN / 32, D_DIM / 32, H_NUM), tblk>>>(
        V, E_DIM, (size_t)D_DIM, VTH, nullptr, SW, (size_t)D_DIM * SW);

    // scores: 1-pass, fused causal mask + exp(x/16 - 2) epilogue -> unnormalized fp16 E (PH)
    gemm_ls<true, false, 1, 3><<<dim3(S_LEN / BN, S_LEN / BM, H_NUM), b256, SMEM_GEMM>>>(
        QH, QH, EW, (size_t)(D_DIM / 2),
        KH, nullptr, EW, (size_t)(D_DIM / 2),
        nullptr, PH, nullptr, SW, (size_t)S_LEN * SW, D_DIM, 0.0625f, nullptr, nullptr);

    // per-row 1/sum of E
    rowsum<<<dim3(S_LEN, H_NUM), dim3(128)>>>(PH, RS);

    // PV: 1-pass (E fp16; V fp16), epilogue scales rows by 1/sum -> AH
    gemm_ls<false, true, 1, 1><<<dim3(D_DIM / BN, S_LEN / BM, H_NUM), b256, SMEM_GEMM>>>(
        PH, PH, SW, (size_t)S_LEN * SW,
        VTH, nullptr, SW, (size_t)D_DIM * SW,
        nullptr, AH, nullptr, EW, (size_t)(D_DIM / 2), S_LEN, 1.f, nullptr, RS);

    // out = attn @ wo: 1-pass, f32 out
    tsplit<<<gw, tblk>>>(wo, E_DIM, 0, WH, nullptr, EW, 0);
    gemm_ls<false, false, 1, 0><<<gproj, b256, SMEM_GEMM>>>(
        AH, AH, EW, 0, WH, nullptr, EW, 0, out, nullptr, nullptr, E_DIM, 0, E_DIM, 1.f, nullptr, nullptr);
}

// round 15
// speedup vs baseline: 1.4902x; 1.4902x over previous
#include <cuda_runtime.h>
#include <cuda_fp16.h>
#include <cstdint>
#include <cstddef>

#define S_LEN 2048
#define E_DIM 4096
#define H_NUM 16
#define D_DIM 256
#define RD_DIM 64
#define EW (E_DIM / 2)   // u32 words per E row
#define SW (S_LEN / 2)   // u32 words per S row
#define WPL ((size_t)E_DIM * EW)   // words per weight plane

// ---------------- scratch ----------------
__device__ __align__(16) float g_V[(size_t)S_LEN * E_DIM];
__device__ __align__(16) float g_P[(size_t)H_NUM * S_LEN * S_LEN];

__device__ __align__(16) uint32_t g_HH[(size_t)S_LEN * EW];
__device__ __align__(16) uint32_t g_QH[(size_t)S_LEN * EW];
__device__ __align__(16) uint32_t g_KH[(size_t)S_LEN * EW];
__device__ __align__(16) uint32_t g_AH[(size_t)S_LEN * EW];
__device__ __align__(16) uint32_t g_WH[4 * WPL];               // q, k, v, o planes
__device__ __align__(16) uint32_t g_VTH[(size_t)H_NUM * D_DIM * SW];
__device__ __align__(16) uint32_t g_PH[(size_t)H_NUM * S_LEN * SW];

// ---------------- helpers ----------------
__device__ __forceinline__ uint32_t pack_split(float x, float y, uint32_t& lo) {
    __half2 h = __floats2half2_rn(x, y);
    float rx = x - __half2float(h.x);
    float ry = y - __half2float(h.y);
    __half2 l = __floats2half2_rn(rx, ry);
    lo = *reinterpret_cast<uint32_t*>(&l);
    return *reinterpret_cast<uint32_t*>(&h);
}

__device__ __forceinline__ uint32_t pack_f16(float x, float y) {
    __half2 h = __floats2half2_rn(x, y);
    return *reinterpret_cast<uint32_t*>(&h);
}

__device__ __forceinline__ uint32_t smem_u32(const void* p) {
    uint32_t a;
    asm("{ .reg .u64 t; cvta.to.shared.u64 t, %1; cvt.u32.u64 %0, t; }" : "=r"(a) : "l"(p));
    return a;
}

__device__ __forceinline__ void mma16(float c[4], const uint32_t a[4],
                                      uint32_t b0, uint32_t b1) {
    asm volatile(
        "mma.sync.aligned.m16n8k16.row.col.f32.f16.f16.f32 "
        "{%0,%1,%2,%3},{%4,%5,%6,%7},{%8,%9},{%0,%1,%2,%3};\n"
        : "+f"(c[0]), "+f"(c[1]), "+f"(c[2]), "+f"(c[3])
        : "r"(a[0]), "r"(a[1]), "r"(a[2]), "r"(a[3]), "r"(b0), "r"(b1));
}

__device__ __forceinline__ void ldsm4(uint32_t r[4], uint32_t addr) {
    asm volatile("ldmatrix.sync.aligned.m8n8.x4.shared.b16 {%0,%1,%2,%3}, [%4];"
                 : "=r"(r[0]), "=r"(r[1]), "=r"(r[2]), "=r"(r[3]) : "r"(addr));
}

__device__ __forceinline__ void cpa16(uint32_t dst, const uint32_t* src) {
    asm volatile("cp.async.cg.shared.global [%0], [%1], 16;" :: "r"(dst), "l"(src));
}
__device__ __forceinline__ void cpa_commit() {
    asm volatile("cp.async.commit_group;" ::: "memory");
}
template<int N>
__device__ __forceinline__ void cpa_wait() {
    asm volatile("cp.async.wait_group %0;" :: "n"(N) : "memory");
}

// ---------------- GEMM: 128 x 256 C tiles, mma.sync + ldmatrix, fp16 multi-pass ----------------
// A: M x K K-major hi/lo planes of fp16x2 words. B: N x K same.
// NPASS==1: acc = A_hi*B_hi
// NPASS==2: acc = A_hi*B_hi + A_lo*B_hi
// NPASS==3: acc = A_hi*B_hi + A_hi*B_lo + A_lo*B_hi
// EPI: 0 = f32 C; 1 = fp16 hi/lo split C (CL may be null); 2 = RoPE + split C.
#define BM 128
#define BN 256
#define ASTR 20
#define A_PL (128 * ASTR)             // 2560
#define B_PL (256 * ASTR)             // 5120
#define STG_W (2 * A_PL + 2 * B_PL)   // 15360 words = 61440 B
#define NSTAGE 3
#define SMEM_GEMM (NSTAGE * STG_W * 4)   // 184320 B

template<bool SKIP_UPPER, bool KLIMIT, int NPASS, int EPI>
__global__ void __launch_bounds__(256, 1)
gemm_ls(const uint32_t* __restrict__ aH, const uint32_t* __restrict__ aL,
        int lda, size_t sA,
        const uint32_t* __restrict__ bH, const uint32_t* __restrict__ bL,
        int ldb, size_t sB,
        float* __restrict__ C, uint32_t* __restrict__ CH, uint32_t* __restrict__ CL,
        int ldc, size_t sC,
        int K, float alpha, const int* __restrict__ pos)
{
    if (SKIP_UPPER && 2 * blockIdx.x > blockIdx.y) return;
    aH += blockIdx.z * sA;  if (NPASS >= 2) aL += blockIdx.z * sA;
    bH += blockIdx.z * sB;  if (NPASS == 3) bL += blockIdx.z * sB;
    if (EPI != 0) { CH += blockIdx.z * sC; if (CL) CL += blockIdx.z * sC; }
    else          { C  += blockIdx.z * sC; }

    const int bm = blockIdx.y * BM;
    const int bn = blockIdx.x * BN;
    const int Keff  = KLIMIT ? min(K, (int)(blockIdx.y + 1) * BM) : K;
    const int niter = Keff >> 5;          // 32 k-elems (16 words) per iter

    extern __shared__ uint32_t sm[];
    const uint32_t sb = smem_u32(sm);

    const int tid  = threadIdx.x;
    const int lane = tid & 31;
    const int warp = tid >> 5;
    const int wm   = (warp >> 2) * 64;    // 2 warps in m
    const int wn   = (warp & 3) * 64;     // 4 warps in n
    const int lr   = lane >> 2;
    const int lc   = lane & 3;

    const uint32_t* aP[2] = { aH + (size_t)bm * lda,
                              (NPASS >= 2) ? aL + (size_t)bm * lda : aH + (size_t)bm * lda };
    const uint32_t* bP[2] = { bH + (size_t)bn * ldb,
                              (NPASS == 3) ? bL + (size_t)bn * ldb : bH + (size_t)bn * ldb };

    const int loffA = ((lane & 15) + wm) * ASTR + ((lane >> 4) << 2);
    const int loffB = ((lane & 7) + ((lane >> 4) << 3) + wn) * ASTR + (((lane >> 3) & 1) << 2);

    auto issue = [&](int it) {
        const int k0w = it << 4;
        const uint32_t stg = sb + (it % NSTAGE) * (STG_W * 4);
        const int nAq = (NPASS >= 2) ? 4 : 2;         // skip AL plane for 1-pass
#pragma unroll
        for (int i = 0; i < 4; i++) {
            if (i >= nAq) break;
            int lin = i * 256 + tid;
            int pl = lin >> 9, rem = lin & 511;
            int row = rem >> 2, q = rem & 3;
            cpa16(stg + (pl * A_PL + row * ASTR + q * 4) * 4,
                  aP[pl] + (size_t)row * lda + k0w + q * 4);
        }
        const int nBq = (NPASS == 3) ? 8 : 4;         // skip BL plane unless 3-pass
#pragma unroll
        for (int i = 0; i < 8; i++) {
            if (i >= nBq) break;
            int lin = i * 256 + tid;
            int pl = lin >> 10, rem = lin & 1023;
            int row = rem >> 2, q = rem & 3;
            cpa16(stg + (2 * A_PL + pl * B_PL + row * ASTR + q * 4) * 4,
                  bP[pl] + (size_t)row * ldb + k0w + q * 4);
        }
        cpa_commit();
    };

    float acc[4][8][4];
#pragma unroll
    for (int i = 0; i < 4; i++)
#pragma unroll
        for (int j = 0; j < 8; j++)
#pragma unroll
            for (int r = 0; r < 4; r++) acc[i][j][r] = 0.f;

    issue(0);
    if (niter > 1) issue(1);

    for (int it = 0; it < niter; ++it) {
        if (it + 2 < niter) { issue(it + 2); cpa_wait<2>(); }
        else if (it + 1 < niter) cpa_wait<1>();
        else cpa_wait<0>();
        __syncthreads();

        const uint32_t stg = sb + (it % NSTAGE) * (STG_W * 4);
        const uint32_t AHs = stg;
        const uint32_t ALs = AHs + A_PL * 4;
        const uint32_t BHs = ALs + A_PL * 4;
        const uint32_t BLs = BHs + B_PL * 4;

#pragma unroll
        for (int kk = 0; kk < 16; kk += 8) {
            uint32_t ah[4][4], al[4][4], bh[4][4], bl[4][4];
#pragma unroll
            for (int mt = 0; mt < 4; mt++) {
                ldsm4(ah[mt], AHs + (loffA + mt * 16 * ASTR + kk) * 4);
                if (NPASS >= 2)
                    ldsm4(al[mt], ALs + (loffA + mt * 16 * ASTR + kk) * 4);
            }
#pragma unroll
            for (int p = 0; p < 4; p++) {
                ldsm4(bh[p], BHs + (loffB + p * 16 * ASTR + kk) * 4);
                if (NPASS == 3)
                    ldsm4(bl[p], BLs + (loffB + p * 16 * ASTR + kk) * 4);
            }
#pragma unroll
            for (int mt = 0; mt < 4; mt++)
#pragma unroll
                for (int p = 0; p < 4; p++) {
#pragma unroll
                    for (int half = 0; half < 2; half++) {
                        int nt = 2 * p + half;
                        uint32_t b0h = bh[p][2 * half], b1h = bh[p][2 * half + 1];
                        mma16(acc[mt][nt], ah[mt], b0h, b1h);
                        if (NPASS >= 2)
                            mma16(acc[mt][nt], al[mt], b0h, b1h);
                        if (NPASS == 3) {
                            uint32_t b0l = bl[p][2 * half], b1l = bl[p][2 * half + 1];
                            mma16(acc[mt][nt], ah[mt], b0l, b1l);
                        }
                    }
                }
        }
        __syncthreads();
    }

    // ---- epilogue ----
#pragma unroll
    for (int mt = 0; mt < 4; mt++) {
        const int r0 = bm + wm + mt * 16 + lr;
        float p0 = 0.f, p1 = 0.f;
        if (EPI == 2) { p0 = (float)pos[r0]; p1 = (float)pos[r0 + 8]; }
#pragma unroll
        for (int nt = 0; nt < 8; nt++) {
            int c0 = bn + wn + nt * 8 + lc * 2;   // even
            float a0 = acc[mt][nt][0], a1 = acc[mt][nt][1];
            float a2 = acc[mt][nt][2], a3 = acc[mt][nt][3];
            if (EPI == 2) {
                int hoff = c0 & (D_DIM - 1);
                if (hoff < RD_DIM) {
                    float inv = exp2f(-0.41524101186092033f * (float)(hoff >> 1));
                    float sn, cs;
                    __sincosf(p0 * inv, &sn, &cs);
                    float t0 = a0 * cs - a1 * sn;
                    a1 = a1 * cs + a0 * sn;  a0 = t0;
                    __sincosf(p1 * inv, &sn, &cs);
                    float t2 = a2 * cs - a3 * sn;
                    a3 = a3 * cs + a2 * sn;  a2 = t2;
                }
            }
            if (EPI != 0) {
                uint32_t lo0, lo1;
                uint32_t hi0 = pack_split(a0 * alpha, a1 * alpha, lo0);
                uint32_t hi1 = pack_split(a2 * alpha, a3 * alpha, lo1);
                size_t o0 = (size_t)r0 * ldc + (c0 >> 1);
                size_t o1 = (size_t)(r0 + 8) * ldc + (c0 >> 1);
                CH[o0] = hi0;
                CH[o1] = hi1;
                if (CL) { CL[o0] = lo0; CL[o1] = lo1; }
            } else {
                float2 v0 = make_float2(a0 * alpha, a1 * alpha);
                float2 v1 = make_float2(a2 * alpha, a3 * alpha);
                *reinterpret_cast<float2*>(C + (size_t)r0 * ldc + c0)       = v0;
                *reinterpret_cast<float2*>(C + (size_t)(r0 + 8) * ldc + c0) = v1;
            }
        }
    }
}

// ---------------- split f32 row-major -> fp16 hi k-pair words ----------------
__global__ void split2(const float* __restrict__ in, uint32_t* __restrict__ oh)
{
    size_t i = (size_t)blockIdx.x * 256 + threadIdx.x;
    float4 v = reinterpret_cast<const float4*>(in)[i];
    reinterpret_cast<uint2*>(oh)[i] = make_uint2(pack_f16(v.x, v.y), pack_f16(v.z, v.w));
}

// ---------------- batched weight transpose+split: 4 weights in one launch ----------------
// in f32 [K][N] -> out fp16 [N][K/2 words]; z selects the weight / output plane.
__global__ void wsplit4(const float* __restrict__ w0, const float* __restrict__ w1,
                        const float* __restrict__ w2, const float* __restrict__ w3,
                        uint32_t* __restrict__ oh)
{
    const float* in = (blockIdx.z == 0) ? w0 : (blockIdx.z == 1) ? w1
                    : (blockIdx.z == 2) ? w2 : w3;
    oh += blockIdx.z * WPL;
    const int k0 = blockIdx.x * 32, n0 = blockIdx.y * 32;
    __shared__ float ts[32][33];
    const int tx = threadIdx.x, ty = threadIdx.y;   // 16 x 16
#pragma unroll
    for (int j = 0; j < 2; j++) {
        float2 v = *reinterpret_cast<const float2*>(
            in + (size_t)(k0 + ty + j * 16) * E_DIM + n0 + tx * 2);
        ts[ty + j * 16][tx * 2]     = v.x;
        ts[ty + j * 16][tx * 2 + 1] = v.y;
    }
    __syncthreads();
#pragma unroll
    for (int j = 0; j < 2; j++) {
        int n = ty + j * 16;
        size_t o = (size_t)(n0 + n) * EW + (k0 >> 1) + tx;
        oh[o] = pack_f16(ts[tx * 2][n], ts[tx * 2 + 1][n]);
    }
}

// ---------------- transpose+split: f32 [K][N] -> fp16 [N][K/2 words] (V per head) ----------------
__global__ void tsplit(const float* __restrict__ in, int ldin, size_t sIn,
                       uint32_t* __restrict__ oh, int ldo, size_t sOut)
{
    in += blockIdx.z * sIn;
    oh += blockIdx.z * sOut;
    const int k0 = blockIdx.x * 32, n0 = blockIdx.y * 32;
    __shared__ float ts[32][33];
    const int tx = threadIdx.x, ty = threadIdx.y;   // 16 x 16
#pragma unroll
    for (int j = 0; j < 2; j++) {
        float2 v = *reinterpret_cast<const float2*>(
            in + (size_t)(k0 + ty + j * 16) * ldin + n0 + tx * 2);
        ts[ty + j * 16][tx * 2]     = v.x;
        ts[ty + j * 16][tx * 2 + 1] = v.y;
    }
    __syncthreads();
#pragma unroll
    for (int j = 0; j < 2; j++) {
        int n = ty + j * 16;
        size_t o = (size_t)(n0 + n) * ldo + (k0 >> 1) + tx;
        oh[o] = pack_f16(ts[tx * 2][n], ts[tx * 2 + 1][n]);
    }
}

// ---------------- causal softmax: smem row buffer -> fp16 P (hi plane only) ----------------
__global__ void softmax_causal(const float* __restrict__ P, uint32_t* __restrict__ PH)
{
    const int m = blockIdx.x, h = blockIdx.y, tid = threadIdx.x;
    const float* row = P + ((size_t)h * S_LEN + m) * S_LEN;
    uint32_t* oh = PH + ((size_t)h * S_LEN + m) * SW;
    const int nv = m + 1;
    const int nfw = ((((m >> 7) + 1) << 7) >> 1);
    __shared__ float rowbuf[S_LEN];
    __shared__ float sh[8];

    float mx = -3.4e38f;
    for (int n = tid; n < nv; n += 256) {
        float v = row[n];
        rowbuf[n] = v;
        mx = fmaxf(mx, v);
    }
#pragma unroll
    for (int o = 16; o; o >>= 1) mx = fmaxf(mx, __shfl_xor_sync(0xffffffffu, mx, o));
    if ((tid & 31) == 0) sh[tid >> 5] = mx;
    __syncthreads();
    float bmax = sh[0];
#pragma unroll
    for (int w = 1; w < 8; w++) bmax = fmaxf(bmax, sh[w]);
    __syncthreads();

    float s = 0.f;
    for (int n = tid; n < nv; n += 256) {
        float e = __expf(rowbuf[n] - bmax);
        rowbuf[n] = e;
        s += e;
    }
#pragma unroll
    for (int o = 16; o; o >>= 1) s += __shfl_xor_sync(0xffffffffu, s, o);
    if ((tid & 31) == 0) sh[tid >> 5] = s;
    __syncthreads();
    float tot = 0.f;
#pragma unroll
    for (int w = 0; w < 8; w++) tot += sh[w];
    float inv = 1.f / tot;
    __syncthreads();

    for (int w = tid; w < nfw; w += 256) {
        int n0 = 2 * w;
        float e0 = (n0     < nv) ? rowbuf[n0]     * inv : 0.f;
        float e1 = (n0 + 1 < nv) ? rowbuf[n0 + 1] * inv : 0.f;
        oh[w] = pack_f16(e0, e1);
    }
}

// ---------------- launch ----------------
extern "C" void kernel_launch(void* const* d_in, const int* in_sizes, int n_in,
                              void* d_out, int out_size)
{
    const float* hidden = (const float*)d_in[0];
    const float* wq     = (const float*)d_in[1];
    const float* wk     = (const float*)d_in[2];
    const float* wv     = (const float*)d_in[3];
    const float* wo     = (const float*)d_in[4];
    const int*   pos    = (const int*)d_in[5];
    float* out = (float*)d_out;

    float *V, *P;
    uint32_t *HH, *QH, *KH, *AH, *WH, *VTH, *PH;
    cudaGetSymbolAddress((void**)&V, g_V);
    cudaGetSymbolAddress((void**)&P, g_P);
    cudaGetSymbolAddress((void**)&HH, g_HH);
    cudaGetSymbolAddress((void**)&QH, g_QH);
    cudaGetSymbolAddress((void**)&KH, g_KH);
    cudaGetSymbolAddress((void**)&AH, g_AH);
    cudaGetSymbolAddress((void**)&WH, g_WH);
    cudaGetSymbolAddress((void**)&VTH, g_VTH);
    cudaGetSymbolAddress((void**)&PH, g_PH);

    cudaFuncSetAttribute(gemm_ls<false, false, 1, 2>, cudaFuncAttributeMaxDynamicSharedMemorySize, SMEM_GEMM);
    cudaFuncSetAttribute(gemm_ls<false, false, 1, 0>, cudaFuncAttributeMaxDynamicSharedMemorySize, SMEM_GEMM);
    cudaFuncSetAttribute(gemm_ls<true,  false, 1, 0>, cudaFuncAttributeMaxDynamicSharedMemorySize, SMEM_GEMM);
    cudaFuncSetAttribute(gemm_ls<false, true,  1, 1>, cudaFuncAttributeMaxDynamicSharedMemorySize, SMEM_GEMM);

    const dim3 b256(256);
    const dim3 tblk(16, 16);
    const dim3 gproj(E_DIM / BN, S_LEN / BM, 1);
    const int nsplit = (S_LEN * E_DIM / 4) / 256;

    uint32_t* WHq = WH;
    uint32_t* WHk = WH + WPL;
    uint32_t* WHv = WH + 2 * WPL;
    uint32_t* WHo = WH + 3 * WPL;

    // hidden -> fp16 ; all four weights transposed+split in one launch
    split2<<<nsplit, b256>>>(hidden, HH);
    wsplit4<<<dim3(E_DIM / 32, E_DIM / 32, 4), tblk>>>(wq, wk, wv, wo, WH);

    // Q projection: 1-pass, fused RoPE epilogue -> QH
    gemm_ls<false, false, 1, 2><<<gproj, b256, SMEM_GEMM>>>(
        HH, HH, EW, 0, WHq, nullptr, EW, 0, nullptr, QH, nullptr, EW, 0, E_DIM, 1.f, pos);

    // K projection: 1-pass, fused RoPE epilogue -> KH
    gemm_ls<false, false, 1, 2><<<gproj, b256, SMEM_GEMM>>>(
        HH, HH, EW, 0, WHk, nullptr, EW, 0, nullptr, KH, nullptr, EW, 0, E_DIM, 1.f, pos);

    // V projection: 1-pass, f32 out
    gemm_ls<false, false, 1, 0><<<gproj, b256, SMEM_GEMM>>>(
        HH, HH, EW, 0, WHv, nullptr, EW, 0, V, nullptr, nullptr, E_DIM, 0, E_DIM, 1.f, nullptr);

    // V transpose+split per head
    tsplit<<<dim3(S_LEN / 32, D_DIM / 32, H_NUM), tblk>>>(
        V, E_DIM, (size_t)D_DIM, VTH, SW, (size_t)D_DIM * SW);

    // scores: 1-pass (Q fp16; K fp16) -> f32 P
    gemm_ls<true, false, 1, 0><<<dim3(S_LEN / BN, S_LEN / BM, H_NUM), b256, SMEM_GEMM>>>(
        QH, QH, EW, (size_t)(D_DIM / 2),
        KH, nullptr, EW, (size_t)(D_DIM / 2),
        P, nullptr, nullptr, S_LEN, (size_t)S_LEN * S_LEN, D_DIM, 0.0625f, nullptr);

    softmax_causal<<<dim3(S_LEN, H_NUM), b256>>>(P, PH);

    // PV: 1-pass (P fp16; V fp16), split epilogue -> AH
    gemm_ls<false, true, 1, 1><<<dim3(D_DIM / BN, S_LEN / BM, H_NUM), b256, SMEM_GEMM>>>(
        PH, PH, SW, (size_t)S_LEN * SW,
        VTH, nullptr, SW, (size_t)D_DIM * SW,
        nullptr, AH, nullptr, EW, (size_t)(D_DIM / 2), S_LEN, 1.f, nullptr);

    // out = attn @ wo: 1-pass, f32 out
    gemm_ls<false, false, 1, 0><<<gproj, b256, SMEM_GEMM>>>(
        AH, AH, EW, 0, WHo, nullptr, EW, 0, out, nullptr, nullptr, E_DIM, 0, E_DIM, 1.f, nullptr);
}